// round 2
// baseline (speedup 1.0000x reference)
#include <cuda_runtime.h>
#include <cuda_bf16.h>
#include <cstdint>

#define N_NODES 100000
#define N_GRAPHS 64
#define MAX_E    1600000

// ---------------- scratch (device globals; no allocation allowed) ----------
__device__ int   g_flag64;               // 1 if index buffers are int64
__device__ int   g_src[MAX_E];
__device__ int   g_dst[MAX_E];
__device__ int   g_batch[N_NODES];
__device__ int   g_deg[N_NODES];
__device__ float g_dinv[N_NODES];
__device__ __align__(16) float g_h[N_NODES * 64];     // activations
__device__ __align__(16) float g_agg[N_NODES * 64];   // aggregation / GEMM scratch
__device__ __align__(16) float g_t[N_NODES * 24];     // layer-3 aggregated output
__device__ float g_sums[N_GRAPHS * 24];
__device__ float g_cnt[N_GRAPHS];
__device__ float g_zero24[24];          // zero-initialized, never written

// ---------------- dtype detection + index conversion ------------------------
// If the underlying buffer is int64 (values < 2^31, nonnegative), every odd
// 32-bit word is zero. For int32 data uniform in [0, 1e5), 2048 samples make
// a false "all zero" impossible in practice.
__global__ void detect_dtype_kernel(const int* __restrict__ buf, int nelem) {
    int nz = 0;
    int samples = nelem < 2048 ? nelem : 2048;
    for (int i = 0; i < samples; i++) nz |= buf[2 * i + 1];
    g_flag64 = (nz == 0) ? 1 : 0;
}

__global__ void convert_edges_kernel(const int* __restrict__ buf, int E) {
    int e = blockIdx.x * blockDim.x + threadIdx.x;
    if (e >= E) return;
    if (g_flag64) {
        g_src[e] = buf[2 * e];
        g_dst[e] = buf[2 * (E + e)];
    } else {
        g_src[e] = buf[e];
        g_dst[e] = buf[E + e];
    }
}

__global__ void convert_batch_kernel(const int* __restrict__ buf) {
    int v = blockIdx.x * blockDim.x + threadIdx.x;
    if (v >= N_NODES) return;
    g_batch[v] = g_flag64 ? buf[2 * v] : buf[v];
}

// ---------------- degree / norm --------------------------------------------
__global__ void init_deg_kernel() {
    int v = blockIdx.x * blockDim.x + threadIdx.x;
    if (v < N_NODES) g_deg[v] = 1;   // self-loop
}

__global__ void count_deg_kernel(int E) {
    int e = blockIdx.x * blockDim.x + threadIdx.x;
    if (e < E) atomicAdd(&g_deg[g_dst[e]], 1);
}

__global__ void dinv_kernel() {
    int v = blockIdx.x * blockDim.x + threadIdx.x;
    if (v < N_NODES) g_dinv[v] = rsqrtf((float)g_deg[v]);
}

// ---------------- self-loop term: out[v] = dinv[v]^2 * x[v] (initializes out)
template <int D>
__global__ void selfterm_kernel(const float* __restrict__ x, float* __restrict__ out) {
    long long idx = (long long)blockIdx.x * blockDim.x + threadIdx.x;
    if (idx < (long long)N_NODES * D) {
        int v = (int)(idx / D);
        float di = g_dinv[v];
        out[idx] = di * di * x[idx];
    }
}

// ---------------- edge scatter, D % 4 == 0, one thread per (edge, 4-feature chunk)
template <int D>
__global__ void scatter_kernel(int E, const float* __restrict__ x,
                               float* __restrict__ out) {
    constexpr int CH = D / 4;
    long long idx = (long long)blockIdx.x * blockDim.x + threadIdx.x;
    long long total = (long long)E * CH;
    if (idx >= total) return;
    int e = (int)(idx / CH);
    int c = (int)(idx % CH);
    int s = g_src[e];
    int d = g_dst[e];
    float nrm = g_dinv[s] * g_dinv[d];
    float4 xv = *(const float4*)(x + (long long)s * D + c * 4);
    float* o = out + (long long)d * D + c * 4;
    atomicAdd(o + 0, nrm * xv.x);
    atomicAdd(o + 1, nrm * xv.y);
    atomicAdd(o + 2, nrm * xv.z);
    atomicAdd(o + 3, nrm * xv.w);
}

// ---------------- edge scatter, D = 3 (pos), one thread per edge ------------
__global__ void scatter3_kernel(int E, const float* __restrict__ x,
                                float* __restrict__ out) {
    int e = blockIdx.x * blockDim.x + threadIdx.x;
    if (e >= E) return;
    int s = g_src[e];
    int d = g_dst[e];
    float nrm = g_dinv[s] * g_dinv[d];
    const float* xs = x + (long long)s * 3;
    float* o = out + (long long)d * 3;
    atomicAdd(o + 0, nrm * xs[0]);
    atomicAdd(o + 1, nrm * xs[1]);
    atomicAdd(o + 2, nrm * xs[2]);
}

// ---------------- dense GEMM: out[N,DOUT] = act(in[N,DIN] @ W + b) ----------
template <int DIN, int DOUT, bool RELU>
__global__ void __launch_bounds__(128)
gemm_kernel(const float* __restrict__ in, const float* __restrict__ W,
            const float* __restrict__ b, float* __restrict__ out) {
    __shared__ float sW[DIN * DOUT];
    __shared__ float sb[DOUT];
    for (int i = threadIdx.x; i < DIN * DOUT; i += blockDim.x) sW[i] = W[i];
    for (int i = threadIdx.x; i < DOUT; i += blockDim.x) sb[i] = b[i];
    __syncthreads();
    int v = blockIdx.x * blockDim.x + threadIdx.x;
    if (v >= N_NODES) return;
    float acc[DOUT];
#pragma unroll
    for (int j = 0; j < DOUT; j++) acc[j] = sb[j];
    const float* xr = in + (long long)v * DIN;
#pragma unroll
    for (int k = 0; k < DIN; k++) {
        float x = xr[k];
#pragma unroll
        for (int j = 0; j < DOUT; j++) acc[j] = fmaf(x, sW[k * DOUT + j], acc[j]);
    }
    float* o = out + (long long)v * DOUT;
#pragma unroll
    for (int j = 0; j < DOUT; j++) o[j] = RELU ? fmaxf(acc[j], 0.0f) : acc[j];
}

// ---------------- pooling ----------------------------------------------------
__global__ void zero_pool_kernel() {
    int i = blockIdx.x * blockDim.x + threadIdx.x;
    if (i < N_GRAPHS * 24) g_sums[i] = 0.0f;
    if (i < N_GRAPHS) g_cnt[i] = 0.0f;
}

__global__ void pool_kernel() {
    __shared__ float ssum[N_GRAPHS * 24];
    __shared__ float scnt[N_GRAPHS];
    for (int i = threadIdx.x; i < N_GRAPHS * 24; i += blockDim.x) ssum[i] = 0.0f;
    for (int i = threadIdx.x; i < N_GRAPHS; i += blockDim.x) scnt[i] = 0.0f;
    __syncthreads();
    int v = blockIdx.x * blockDim.x + threadIdx.x;
    if (v < N_NODES) {
        int g = g_batch[v];
        const float* tr = g_t + (long long)v * 24;
#pragma unroll
        for (int j = 0; j < 24; j++) atomicAdd(&ssum[g * 24 + j], tr[j]);
        atomicAdd(&scnt[g], 1.0f);
    }
    __syncthreads();
    for (int i = threadIdx.x; i < N_GRAPHS * 24; i += blockDim.x)
        if (ssum[i] != 0.0f) atomicAdd(&g_sums[i], ssum[i]);
    for (int i = threadIdx.x; i < N_GRAPHS; i += blockDim.x)
        if (scnt[i] != 0.0f) atomicAdd(&g_cnt[i], scnt[i]);
}

__global__ void final_kernel(const float* __restrict__ b3, float* __restrict__ out) {
    int i = blockIdx.x * blockDim.x + threadIdx.x;
    if (i >= N_GRAPHS * 24) return;
    int g = i / 24;
    int j = i % 24;
    float c = g_cnt[g];
    float m = (c > 0.0f) ? (g_sums[i] / c + b3[j]) : 0.0f;
    out[i] = tanhf(m);
}

// ---------------- launch -----------------------------------------------------
extern "C" void kernel_launch(void* const* d_in, const int* in_sizes, int n_in,
                              void* d_out, int out_size) {
    const float* pos   = (const float*)d_in[0];
    const int*   ei    = (const int*)d_in[1];   // int32 or int64 (detected)
    const int*   batch = (const int*)d_in[2];
    const float* W1    = (const float*)d_in[3];
    const float* b1    = (const float*)d_in[4];
    const float* W2    = (const float*)d_in[5];
    const float* b2    = (const float*)d_in[6];
    const float* W3    = (const float*)d_in[7];
    const float* b3    = (const float*)d_in[8];
    float*       out   = (float*)d_out;

    const int E = in_sizes[1] / 2;

    float* zero24; cudaGetSymbolAddress((void**)&zero24, g_zero24);
    float* h;      cudaGetSymbolAddress((void**)&h, g_h);
    float* agg;    cudaGetSymbolAddress((void**)&agg, g_agg);
    float* t;      cudaGetSymbolAddress((void**)&t, g_t);

    const int TB = 256;
    auto grid = [&](long long n, int tb) { return (int)((n + tb - 1) / tb); };

    // dtype detection + index conversion
    detect_dtype_kernel<<<1, 1>>>(ei, in_sizes[1] / 2 < 2048 ? in_sizes[1] / 2 : 2048 * 2);
    convert_edges_kernel<<<grid(E, TB), TB>>>(ei, E);
    convert_batch_kernel<<<grid(N_NODES, TB), TB>>>(batch);

    // normalization
    init_deg_kernel<<<grid(N_NODES, TB), TB>>>();
    count_deg_kernel<<<grid(E, TB), TB>>>(E);
    dinv_kernel<<<grid(N_NODES, TB), TB>>>();

    // layer 1: aggregate pos (dim 3) first, then GEMM 3->64 + relu
    selfterm_kernel<3><<<grid((long long)N_NODES * 3, TB), TB>>>(pos, agg);
    scatter3_kernel<<<grid(E, TB), TB>>>(E, pos, agg);
    gemm_kernel<3, 64, true><<<grid(N_NODES, 128), 128>>>(agg, W1, b1, h);

    // layer 2: aggregate h (dim 64), GEMM 64->64 + relu
    selfterm_kernel<64><<<grid((long long)N_NODES * 64, TB), TB>>>(h, agg);
    scatter_kernel<64><<<grid((long long)E * 16, TB), TB>>>(E, h, agg);
    gemm_kernel<64, 64, true><<<grid(N_NODES, 128), 128>>>(agg, W2, b2, h);

    // layer 3: GEMM 64->24 (no bias), then aggregate (dim 24)
    gemm_kernel<64, 24, false><<<grid(N_NODES, 128), 128>>>(h, W3, zero24, agg);
    selfterm_kernel<24><<<grid((long long)N_NODES * 24, TB), TB>>>(agg, t);
    scatter_kernel<24><<<grid((long long)E * 6, TB), TB>>>(E, agg, t);

    // pooling + bias + tanh
    zero_pool_kernel<<<grid(N_GRAPHS * 24, TB), TB>>>();
    pool_kernel<<<grid(N_NODES, TB), TB>>>();
    final_kernel<<<grid(N_GRAPHS * 24, TB), TB>>>(b3, out);
}

// round 3
// speedup vs baseline: 1.8465x; 1.8465x over previous
#include <cuda_runtime.h>
#include <cuda_bf16.h>
#include <cstdint>

#define N_NODES 100000
#define N_GRAPHS 64
#define MAX_E    1600000
#define SCAN_B   1024
#define N_SCANB  ((N_NODES + SCAN_B - 1) / SCAN_B)   // 98

// ---------------- scratch (device globals; no allocation allowed) ----------
__device__ int   g_flag64;               // 1 if index buffers are int64
__device__ int   g_batch[N_NODES];
__device__ int   g_indeg[N_NODES];
__device__ float g_dinv[N_NODES];
__device__ int   g_row_ptr[N_NODES + 1];
__device__ int   g_cur[N_NODES];
__device__ int   g_blocksum[N_SCANB];
__device__ int   g_blockoff[N_SCANB];
__device__ int   g_csr_src[MAX_E];
__device__ float g_csr_nrm[MAX_E];
__device__ __align__(16) float g_h[N_NODES * 64];     // activations
__device__ __align__(16) float g_agg[N_NODES * 64];   // aggregation / GEMM scratch
__device__ __align__(16) float g_t[N_NODES * 24];     // layer-3 aggregated output
__device__ float g_sums[N_GRAPHS * 24];
__device__ float g_cnt[N_GRAPHS];
__device__ float g_zero24[24];          // zero-initialized, never written

// ---------------- dtype detection --------------------------------------------
// int64 indices (< 2^31) => every odd 32-bit word is zero.
__global__ void detect_dtype_kernel(const int* __restrict__ buf, int samples) {
    int nz = 0;
    for (int i = 0; i < samples; i++) nz |= buf[2 * i + 1];
    g_flag64 = (nz == 0) ? 1 : 0;
}

__device__ __forceinline__ int load_idx(const int* __restrict__ buf, long long i) {
    return g_flag64 ? buf[2 * i] : buf[(int)i];
}

__global__ void convert_batch_kernel(const int* __restrict__ buf) {
    int v = blockIdx.x * blockDim.x + threadIdx.x;
    if (v < N_NODES) g_batch[v] = load_idx(buf, v);
}

// ---------------- degree ------------------------------------------------------
__global__ void zero_indeg_kernel() {
    int v = blockIdx.x * blockDim.x + threadIdx.x;
    if (v < N_NODES) g_indeg[v] = 0;
}

__global__ void count_deg_kernel(const int* __restrict__ ei, int E) {
    int e = blockIdx.x * blockDim.x + threadIdx.x;
    if (e < E) {
        int d = load_idx(ei, (long long)E + e);
        atomicAdd(&g_indeg[d], 1);
    }
}

// ---------------- scan (exclusive prefix sum of indeg -> row_ptr) -------------
__global__ void scan1_kernel() {
    __shared__ int s[SCAN_B];
    int t = threadIdx.x;
    int i = blockIdx.x * SCAN_B + t;
    int v = (i < N_NODES) ? g_indeg[i] : 0;
    if (i < N_NODES) g_dinv[i] = rsqrtf((float)(v + 1));   // fused: +1 self-loop
    s[t] = v;
    __syncthreads();
#pragma unroll
    for (int off = 1; off < SCAN_B; off <<= 1) {
        int x = (t >= off) ? s[t - off] : 0;
        __syncthreads();
        s[t] += x;
        __syncthreads();
    }
    if (i < N_NODES) g_row_ptr[i] = s[t] - v;   // exclusive
    if (t == SCAN_B - 1) g_blocksum[blockIdx.x] = s[t];
}

__global__ void scan2_kernel() {
    if (threadIdx.x == 0) {
        int acc = 0;
        for (int b = 0; b < N_SCANB; b++) {
            g_blockoff[b] = acc;
            acc += g_blocksum[b];
        }
    }
}

__global__ void scan3_kernel(int E) {
    int i = blockIdx.x * blockDim.x + threadIdx.x;
    if (i < N_NODES) {
        int r = g_row_ptr[i] + g_blockoff[i / SCAN_B];
        g_row_ptr[i] = r;
        g_cur[i] = r;
    }
    if (i == 0) g_row_ptr[N_NODES] = E;
}

// ---------------- CSR fill ----------------------------------------------------
__global__ void fill_csr_kernel(const int* __restrict__ ei, int E) {
    int e = blockIdx.x * blockDim.x + threadIdx.x;
    if (e >= E) return;
    int s = load_idx(ei, e);
    int d = load_idx(ei, (long long)E + e);
    int pos = atomicAdd(&g_cur[d], 1);
    g_csr_src[pos] = s;
    g_csr_nrm[pos] = g_dinv[s] * g_dinv[d];
}

// ---------------- gather aggregation: dim 3 (thread per node) ------------------
__global__ void gather3_kernel(const float* __restrict__ x, float* __restrict__ out) {
    int v = blockIdx.x * blockDim.x + threadIdx.x;
    if (v >= N_NODES) return;
    float di = g_dinv[v];
    float self = di * di;
    float a0 = self * x[3 * v + 0];
    float a1 = self * x[3 * v + 1];
    float a2 = self * x[3 * v + 2];
    int beg = g_row_ptr[v], end = g_row_ptr[v + 1];
    for (int e = beg; e < end; e++) {
        int s = g_csr_src[e];
        float nrm = g_csr_nrm[e];
        a0 = fmaf(nrm, x[3 * s + 0], a0);
        a1 = fmaf(nrm, x[3 * s + 1], a1);
        a2 = fmaf(nrm, x[3 * s + 2], a2);
    }
    out[3 * v + 0] = a0;
    out[3 * v + 1] = a1;
    out[3 * v + 2] = a2;
}

// ---------------- gather aggregation: dim 64 (warp per node) -------------------
__global__ void __launch_bounds__(256)
gather64_kernel(const float* __restrict__ x, float* __restrict__ out) {
    int gtid = blockIdx.x * blockDim.x + threadIdx.x;
    int v = gtid >> 5;
    int lane = gtid & 31;
    if (v >= N_NODES) return;
    float di = g_dinv[v];
    float self = di * di;
    const float* xr = x + (long long)v * 64;
    float a0 = self * xr[lane];
    float a1 = self * xr[lane + 32];
    int beg = g_row_ptr[v], end = g_row_ptr[v + 1];
#pragma unroll 2
    for (int e = beg; e < end; e++) {
        int s = g_csr_src[e];
        float nrm = g_csr_nrm[e];
        const float* xs = x + (long long)s * 64;
        a0 = fmaf(nrm, xs[lane], a0);
        a1 = fmaf(nrm, xs[lane + 32], a1);
    }
    float* o = out + (long long)v * 64;
    o[lane] = a0;
    o[lane + 32] = a1;
}

// ---------------- gather aggregation: dim 24 (warp per node, lanes<24) ---------
__global__ void __launch_bounds__(256)
gather24_kernel(const float* __restrict__ x, float* __restrict__ out) {
    int gtid = blockIdx.x * blockDim.x + threadIdx.x;
    int v = gtid >> 5;
    int lane = gtid & 31;
    if (v >= N_NODES || lane >= 24) return;
    float di = g_dinv[v];
    float self = di * di;
    float a = self * x[(long long)v * 24 + lane];
    int beg = g_row_ptr[v], end = g_row_ptr[v + 1];
#pragma unroll 2
    for (int e = beg; e < end; e++) {
        int s = g_csr_src[e];
        float nrm = g_csr_nrm[e];
        a = fmaf(nrm, x[(long long)s * 24 + lane], a);
    }
    out[(long long)v * 24 + lane] = a;
}

// ---------------- dense GEMM: out[N,DOUT] = act(in[N,DIN] @ W + b) ----------
template <int DIN, int DOUT, bool RELU>
__global__ void __launch_bounds__(128)
gemm_kernel(const float* __restrict__ in, const float* __restrict__ W,
            const float* __restrict__ b, float* __restrict__ out) {
    __shared__ float sW[DIN * DOUT];
    __shared__ float sb[DOUT];
    for (int i = threadIdx.x; i < DIN * DOUT; i += blockDim.x) sW[i] = W[i];
    for (int i = threadIdx.x; i < DOUT; i += blockDim.x) sb[i] = b[i];
    __syncthreads();
    int v = blockIdx.x * blockDim.x + threadIdx.x;
    if (v >= N_NODES) return;
    float acc[DOUT];
#pragma unroll
    for (int j = 0; j < DOUT; j++) acc[j] = sb[j];
    const float* xr = in + (long long)v * DIN;
    if constexpr (DIN % 4 == 0) {
#pragma unroll
        for (int k4 = 0; k4 < DIN / 4; k4++) {
            float4 xv = *(const float4*)(xr + k4 * 4);
            float xs[4] = {xv.x, xv.y, xv.z, xv.w};
#pragma unroll
            for (int kk = 0; kk < 4; kk++) {
                float xk = xs[kk];
                int k = k4 * 4 + kk;
#pragma unroll
                for (int j = 0; j < DOUT; j++) acc[j] = fmaf(xk, sW[k * DOUT + j], acc[j]);
            }
        }
    } else {
#pragma unroll
        for (int k = 0; k < DIN; k++) {
            float xk = xr[k];
#pragma unroll
            for (int j = 0; j < DOUT; j++) acc[j] = fmaf(xk, sW[k * DOUT + j], acc[j]);
        }
    }
    float* o = out + (long long)v * DOUT;
    if constexpr (DOUT % 4 == 0) {
#pragma unroll
        for (int j4 = 0; j4 < DOUT / 4; j4++) {
            float4 r;
            r.x = RELU ? fmaxf(acc[j4 * 4 + 0], 0.0f) : acc[j4 * 4 + 0];
            r.y = RELU ? fmaxf(acc[j4 * 4 + 1], 0.0f) : acc[j4 * 4 + 1];
            r.z = RELU ? fmaxf(acc[j4 * 4 + 2], 0.0f) : acc[j4 * 4 + 2];
            r.w = RELU ? fmaxf(acc[j4 * 4 + 3], 0.0f) : acc[j4 * 4 + 3];
            *(float4*)(o + j4 * 4) = r;
        }
    } else {
#pragma unroll
        for (int j = 0; j < DOUT; j++) o[j] = RELU ? fmaxf(acc[j], 0.0f) : acc[j];
    }
}

// ---------------- pooling ----------------------------------------------------
__global__ void zero_pool_kernel() {
    int i = blockIdx.x * blockDim.x + threadIdx.x;
    if (i < N_GRAPHS * 24) g_sums[i] = 0.0f;
    if (i < N_GRAPHS) g_cnt[i] = 0.0f;
}

__global__ void pool_kernel() {
    __shared__ float ssum[N_GRAPHS * 24];
    __shared__ float scnt[N_GRAPHS];
    for (int i = threadIdx.x; i < N_GRAPHS * 24; i += blockDim.x) ssum[i] = 0.0f;
    for (int i = threadIdx.x; i < N_GRAPHS; i += blockDim.x) scnt[i] = 0.0f;
    __syncthreads();
    int v = blockIdx.x * blockDim.x + threadIdx.x;
    if (v < N_NODES) {
        int g = g_batch[v];
        const float* tr = g_t + (long long)v * 24;
#pragma unroll
        for (int j = 0; j < 24; j++) atomicAdd(&ssum[g * 24 + j], tr[j]);
        atomicAdd(&scnt[g], 1.0f);
    }
    __syncthreads();
    for (int i = threadIdx.x; i < N_GRAPHS * 24; i += blockDim.x)
        if (ssum[i] != 0.0f) atomicAdd(&g_sums[i], ssum[i]);
    for (int i = threadIdx.x; i < N_GRAPHS; i += blockDim.x)
        if (scnt[i] != 0.0f) atomicAdd(&g_cnt[i], scnt[i]);
}

__global__ void final_kernel(const float* __restrict__ b3, float* __restrict__ out) {
    int i = blockIdx.x * blockDim.x + threadIdx.x;
    if (i >= N_GRAPHS * 24) return;
    int g = i / 24;
    int j = i % 24;
    float c = g_cnt[g];
    float m = (c > 0.0f) ? (g_sums[i] / c + b3[j]) : 0.0f;
    out[i] = tanhf(m);
}

// ---------------- launch -----------------------------------------------------
extern "C" void kernel_launch(void* const* d_in, const int* in_sizes, int n_in,
                              void* d_out, int out_size) {
    const float* pos   = (const float*)d_in[0];
    const int*   ei    = (const int*)d_in[1];   // int32 or int64 (detected)
    const int*   batch = (const int*)d_in[2];
    const float* W1    = (const float*)d_in[3];
    const float* b1    = (const float*)d_in[4];
    const float* W2    = (const float*)d_in[5];
    const float* b2    = (const float*)d_in[6];
    const float* W3    = (const float*)d_in[7];
    const float* b3    = (const float*)d_in[8];
    float*       out   = (float*)d_out;

    const int E = in_sizes[1] / 2;

    float* zero24; cudaGetSymbolAddress((void**)&zero24, g_zero24);
    float* h;      cudaGetSymbolAddress((void**)&h, g_h);
    float* agg;    cudaGetSymbolAddress((void**)&agg, g_agg);
    float* t;      cudaGetSymbolAddress((void**)&t, g_t);

    const int TB = 256;
    auto grid = [&](long long n, int tb) { return (int)((n + tb - 1) / tb); };

    // dtype detection + batch conversion
    detect_dtype_kernel<<<1, 1>>>(ei, E < 2048 ? E : 2048);
    convert_batch_kernel<<<grid(N_NODES, TB), TB>>>(batch);

    // degree + norm + CSR build
    zero_indeg_kernel<<<grid(N_NODES, TB), TB>>>();
    count_deg_kernel<<<grid(E, TB), TB>>>(ei, E);
    scan1_kernel<<<N_SCANB, SCAN_B>>>();
    scan2_kernel<<<1, 32>>>();
    scan3_kernel<<<grid(N_NODES, TB), TB>>>(E);
    fill_csr_kernel<<<grid(E, TB), TB>>>(ei, E);

    // layer 1: aggregate pos (dim 3), then GEMM 3->64 + relu
    gather3_kernel<<<grid(N_NODES, TB), TB>>>(pos, agg);
    gemm_kernel<3, 64, true><<<grid(N_NODES, 128), 128>>>(agg, W1, b1, h);

    // layer 2: aggregate h (dim 64), GEMM 64->64 + relu
    gather64_kernel<<<grid((long long)N_NODES * 32, TB), TB>>>(h, agg);
    gemm_kernel<64, 64, true><<<grid(N_NODES, 128), 128>>>(agg, W2, b2, h);

    // layer 3: GEMM 64->24 (no bias yet), then aggregate (dim 24)
    gemm_kernel<64, 24, false><<<grid(N_NODES, 128), 128>>>(h, W3, zero24, agg);
    gather24_kernel<<<grid((long long)N_NODES * 32, TB), TB>>>(agg, t);

    // pooling + bias + tanh
    zero_pool_kernel<<<grid(N_GRAPHS * 24, TB), TB>>>();
    pool_kernel<<<grid(N_NODES, TB), TB>>>();
    final_kernel<<<grid(N_GRAPHS * 24, TB), TB>>>(b3, out);
}

// round 4
// speedup vs baseline: 2.3461x; 1.2706x over previous
#include <cuda_runtime.h>
#include <cuda_bf16.h>
#include <cstdint>

#define N_NODES 100000
#define N_GRAPHS 64
#define MAX_E    1600000
#define SCAN_B   1024
#define N_SCANB  ((N_NODES + SCAN_B - 1) / SCAN_B)   // 98

// ---------------- scratch (device globals; no allocation allowed) ----------
__device__ int   g_flag64;               // 1 if index buffers are int64
__device__ int   g_batch[N_NODES];
__device__ int   g_indeg[N_NODES];
__device__ float g_dinv[N_NODES];
__device__ int   g_row_ptr[N_NODES + 1];
__device__ int   g_cur[N_NODES];
__device__ int   g_blocksum[N_SCANB];
__device__ int   g_blockoff[N_SCANB];
__device__ __align__(16) int2  g_csr[MAX_E];           // {src, nrm as int}
__device__ __align__(16) float g_h[N_NODES * 64];      // h1 activations
__device__ __align__(16) float g_y[N_NODES * 32];      // layer-3 pre-agg (stride 32, 24 used)
__device__ float g_sums[N_GRAPHS * 24];
__device__ float g_cnt[N_GRAPHS];

// ---------------- detect dtype + zero pool accumulators ---------------------
// int64 indices (< 2^31) => every odd 32-bit word is zero. 2048 samples.
__global__ void detect_zero_kernel(const int* __restrict__ buf, int samples) {
    __shared__ int s_nz[256];
    int t = threadIdx.x;
    int nz = 0;
    for (int i = t; i < samples; i += 256) nz |= buf[2 * i + 1];
    s_nz[t] = nz;
    __syncthreads();
    for (int off = 128; off > 0; off >>= 1) {
        if (t < off) s_nz[t] |= s_nz[t + off];
        __syncthreads();
    }
    if (t == 0) g_flag64 = (s_nz[0] == 0) ? 1 : 0;
    // zero pooling accumulators
    for (int i = t; i < N_GRAPHS * 24; i += 256) g_sums[i] = 0.0f;
    if (t < N_GRAPHS) g_cnt[t] = 0.0f;
}

__device__ __forceinline__ int load_idx(const int* __restrict__ buf, long long i) {
    return g_flag64 ? buf[2 * i] : buf[(int)i];
}

// ---------------- batch convert + per-graph counts + zero indeg -------------
__global__ void convert_kernel(const int* __restrict__ buf) {
    __shared__ float scnt[N_GRAPHS];
    int t = threadIdx.x;
    if (t < N_GRAPHS) scnt[t] = 0.0f;
    __syncthreads();
    int v = blockIdx.x * blockDim.x + t;
    if (v < N_NODES) {
        int g = load_idx(buf, v);
        g_batch[v] = g;
        g_indeg[v] = 0;
        atomicAdd(&scnt[g], 1.0f);
    }
    __syncthreads();
    if (t < N_GRAPHS && scnt[t] != 0.0f) atomicAdd(&g_cnt[t], scnt[t]);
}

// ---------------- degree ------------------------------------------------------
__global__ void count_deg_kernel(const int* __restrict__ ei, int E) {
    int e = blockIdx.x * blockDim.x + threadIdx.x;
    if (e < E) {
        int d = load_idx(ei, (long long)E + e);
        atomicAdd(&g_indeg[d], 1);
    }
}

// ---------------- scan (exclusive prefix sum of indeg -> row_ptr) -------------
__global__ void scan1_kernel() {
    __shared__ int s[SCAN_B];
    int t = threadIdx.x;
    int i = blockIdx.x * SCAN_B + t;
    int v = (i < N_NODES) ? g_indeg[i] : 0;
    if (i < N_NODES) g_dinv[i] = rsqrtf((float)(v + 1));   // +1 self-loop
    s[t] = v;
    __syncthreads();
#pragma unroll
    for (int off = 1; off < SCAN_B; off <<= 1) {
        int x = (t >= off) ? s[t - off] : 0;
        __syncthreads();
        s[t] += x;
        __syncthreads();
    }
    if (i < N_NODES) g_row_ptr[i] = s[t] - v;   // exclusive
    if (t == SCAN_B - 1) g_blocksum[blockIdx.x] = s[t];
}

__global__ void scan2_kernel() {
    if (threadIdx.x == 0) {
        int acc = 0;
        for (int b = 0; b < N_SCANB; b++) {
            g_blockoff[b] = acc;
            acc += g_blocksum[b];
        }
    }
}

__global__ void scan3_kernel(int E) {
    int i = blockIdx.x * blockDim.x + threadIdx.x;
    if (i < N_NODES) {
        int r = g_row_ptr[i] + g_blockoff[i / SCAN_B];
        g_row_ptr[i] = r;
        g_cur[i] = r;
    }
    if (i == 0) g_row_ptr[N_NODES] = E;
}

// ---------------- CSR fill ----------------------------------------------------
__global__ void fill_csr_kernel(const int* __restrict__ ei, int E) {
    int e = blockIdx.x * blockDim.x + threadIdx.x;
    if (e >= E) return;
    int s = load_idx(ei, e);
    int d = load_idx(ei, (long long)E + e);
    int pos = atomicAdd(&g_cur[d], 1);
    float nrm = g_dinv[s] * g_dinv[d];
    g_csr[pos] = make_int2(s, __float_as_int(nrm));
}

// ---------------- layer 1: gather(pos,3) + GEMM 3->64 + ReLU ------------------
__global__ void __launch_bounds__(128)
layer1_kernel(const float* __restrict__ pos, const float* __restrict__ W1,
              const float* __restrict__ b1, float* __restrict__ h1) {
    __shared__ float sW[3 * 64];
    __shared__ float sb[64];
    for (int i = threadIdx.x; i < 3 * 64; i += 128) sW[i] = W1[i];
    if (threadIdx.x < 64) sb[threadIdx.x] = b1[threadIdx.x];
    __syncthreads();
    int v = blockIdx.x * 128 + threadIdx.x;
    if (v >= N_NODES) return;
    float di = g_dinv[v];
    float self = di * di;
    float a0 = self * pos[3 * v + 0];
    float a1 = self * pos[3 * v + 1];
    float a2 = self * pos[3 * v + 2];
    int beg = g_row_ptr[v], end = g_row_ptr[v + 1];
#pragma unroll 2
    for (int e = beg; e < end; e++) {
        int2 p = g_csr[e];
        float nrm = __int_as_float(p.y);
        const float* xs = pos + (long long)p.x * 3;
        a0 = fmaf(nrm, xs[0], a0);
        a1 = fmaf(nrm, xs[1], a1);
        a2 = fmaf(nrm, xs[2], a2);
    }
    float* o = h1 + (long long)v * 64;
#pragma unroll
    for (int j4 = 0; j4 < 16; j4++) {
        float4 r;
        float* rr = (float*)&r;
#pragma unroll
        for (int u = 0; u < 4; u++) {
            int j = j4 * 4 + u;
            float acc = sb[j];
            acc = fmaf(a0, sW[j], acc);
            acc = fmaf(a1, sW[64 + j], acc);
            acc = fmaf(a2, sW[128 + j], acc);
            rr[u] = fmaxf(acc, 0.0f);
        }
        *(float4*)(o + j4 * 4) = r;
    }
}

// ---------------- layer 2+3 GEMM: gather(h1,64) + GEMM64x64 + ReLU + GEMM64x24
#define L2_NPB 64   // nodes per block (8 warps x 8 iterations)
__global__ void __launch_bounds__(256)
layer2_kernel(const float* __restrict__ h1, const float* __restrict__ W2,
              const float* __restrict__ b2, const float* __restrict__ W3,
              float* __restrict__ y) {
    __shared__ float sW2[64 * 64];
    __shared__ float sW3[64 * 24];
    __shared__ float sb2[64];
    __shared__ float tile[8][64];
    int t = threadIdx.x;
    for (int i = t; i < 64 * 64; i += 256) sW2[i] = W2[i];
    for (int i = t; i < 64 * 24; i += 256) sW3[i] = W3[i];
    if (t < 64) sb2[t] = b2[t];
    __syncthreads();
    int warp = t >> 5, lane = t & 31;
#pragma unroll
    for (int it = 0; it < L2_NPB / 8; it++) {
        int v = blockIdx.x * L2_NPB + it * 8 + warp;
        if (v < N_NODES) {
            // gather
            float di = g_dinv[v];
            float self = di * di;
            const float* xr = h1 + (long long)v * 64;
            float a0 = self * xr[lane];
            float a1 = self * xr[lane + 32];
            int beg = g_row_ptr[v], end = g_row_ptr[v + 1];
#pragma unroll 2
            for (int e = beg; e < end; e++) {
                int2 p = g_csr[e];
                float nrm = __int_as_float(p.y);
                const float* xs = h1 + (long long)p.x * 64;
                a0 = fmaf(nrm, xs[lane], a0);
                a1 = fmaf(nrm, xs[lane + 32], a1);
            }
            tile[warp][lane] = a0;
            tile[warp][lane + 32] = a1;
            __syncwarp();
            // GEMM 64x64 + ReLU
            float c0 = sb2[lane], c1 = sb2[lane + 32];
#pragma unroll
            for (int k = 0; k < 64; k++) {
                float xk = tile[warp][k];
                c0 = fmaf(xk, sW2[k * 64 + lane], c0);
                c1 = fmaf(xk, sW2[k * 64 + lane + 32], c1);
            }
            c0 = fmaxf(c0, 0.0f);
            c1 = fmaxf(c1, 0.0f);
            __syncwarp();
            tile[warp][lane] = c0;
            tile[warp][lane + 32] = c1;
            __syncwarp();
            // GEMM 64x24 (bias deferred to final)
            if (lane < 24) {
                float acc = 0.0f;
#pragma unroll
                for (int k = 0; k < 64; k++)
                    acc = fmaf(tile[warp][k], sW3[k * 24 + lane], acc);
                y[(long long)v * 32 + lane] = acc;
            }
            __syncwarp();
        }
    }
}

// ---------------- layer 3 aggregate (dim 24, stride 32) + fused pooling -------
__global__ void __launch_bounds__(256)
gather24_pool_kernel(const float* __restrict__ y) {
    int gtid = blockIdx.x * blockDim.x + threadIdx.x;
    int v = gtid >> 5;
    int lane = gtid & 31;
    if (v >= N_NODES || lane >= 24) return;
    float di = g_dinv[v];
    float self = di * di;
    float a = self * y[(long long)v * 32 + lane];
    int beg = g_row_ptr[v], end = g_row_ptr[v + 1];
#pragma unroll 2
    for (int e = beg; e < end; e++) {
        int2 p = g_csr[e];
        float nrm = __int_as_float(p.y);
        a = fmaf(nrm, y[(long long)p.x * 32 + lane], a);
    }
    int g = g_batch[v];
    atomicAdd(&g_sums[g * 24 + lane], a);
}

// ---------------- final: mean + bias + tanh -----------------------------------
__global__ void final_kernel(const float* __restrict__ b3, float* __restrict__ out) {
    int i = blockIdx.x * blockDim.x + threadIdx.x;
    if (i >= N_GRAPHS * 24) return;
    int g = i / 24;
    int j = i % 24;
    float c = g_cnt[g];
    float m = (c > 0.0f) ? (g_sums[i] / c + b3[j]) : 0.0f;
    out[i] = tanhf(m);
}

// ---------------- launch -----------------------------------------------------
extern "C" void kernel_launch(void* const* d_in, const int* in_sizes, int n_in,
                              void* d_out, int out_size) {
    const float* pos   = (const float*)d_in[0];
    const int*   ei    = (const int*)d_in[1];   // int32 or int64 (detected)
    const int*   batch = (const int*)d_in[2];
    const float* W1    = (const float*)d_in[3];
    const float* b1    = (const float*)d_in[4];
    const float* W2    = (const float*)d_in[5];
    const float* b2    = (const float*)d_in[6];
    const float* W3    = (const float*)d_in[7];
    const float* b3    = (const float*)d_in[8];
    float*       out   = (float*)d_out;

    const int E = in_sizes[1] / 2;

    float* h1; cudaGetSymbolAddress((void**)&h1, g_h);
    float* y;  cudaGetSymbolAddress((void**)&y, g_y);

    const int TB = 256;
    auto grid = [&](long long n, int tb) { return (int)((n + tb - 1) / tb); };

    detect_zero_kernel<<<1, 256>>>(ei, E < 2048 ? E : 2048);
    convert_kernel<<<grid(N_NODES, TB), TB>>>(batch);
    count_deg_kernel<<<grid(E, TB), TB>>>(ei, E);
    scan1_kernel<<<N_SCANB, SCAN_B>>>();
    scan2_kernel<<<1, 32>>>();
    scan3_kernel<<<grid(N_NODES, TB), TB>>>(E);
    fill_csr_kernel<<<grid(E, TB), TB>>>(ei, E);

    layer1_kernel<<<grid(N_NODES, 128), 128>>>(pos, W1, b1, h1);
    layer2_kernel<<<grid(N_NODES, L2_NPB), 256>>>(h1, W2, b2, W3, y);
    gather24_pool_kernel<<<grid((long long)N_NODES * 32, TB), TB>>>(y);
    final_kernel<<<grid(N_GRAPHS * 24, TB), TB>>>(b3, out);
}